// round 5
// baseline (speedup 1.0000x reference)
#include <cuda_runtime.h>
#include <cuda_bf16.h>
#include <stdint.h>
#include <math.h>

#define Bb    8
#define Hh    16
#define NSEQ  1024
#define DMOD  1024
#define DHd   64
#define MR    (Bb * NSEQ)
#define EPSF  1e-9f

typedef unsigned int u32;
typedef unsigned long long u64;
typedef __nv_bfloat16 bf16;

// ---------------- scratch (device globals; allocations forbidden) -----------
__device__ __align__(16) bf16 g_qsH[MR * DMOD], g_qsL[MR * DMOD];
__device__ __align__(16) bf16 g_ksH[MR * DMOD], g_ksL[MR * DMOD];
__device__ __align__(16) bf16 g_vsH[MR * DMOD], g_vsL[MR * DMOD];
__device__ __align__(16) bf16 g_WqH[DMOD * DMOD], g_WqL[DMOD * DMOD];
__device__ __align__(16) bf16 g_WkH[DMOD * DMOD], g_WkL[DMOD * DMOD];
__device__ __align__(16) bf16 g_WvH[DMOD * DMOD], g_WvL[DMOD * DMOD];
__device__ __align__(16) bf16 g_WoH[DMOD * DMOD], g_WoL[DMOD * DMOD];
__device__ __align__(16) bf16 g_WbTH[DMOD * DMOD], g_WbTL[DMOD * DMOD];
__device__ __align__(16) bf16 g_QH[MR * Hh * DHd / 8 * 8], g_QL[MR * Hh * DHd / 8 * 8];
__device__ __align__(16) bf16 g_KH[Bb * Hh * NSEQ * DHd], g_KL[Bb * Hh * NSEQ * DHd];
__device__ __align__(16) bf16 g_VtH[Bb * Hh * DHd * NSEQ], g_VtL[Bb * Hh * DHd * NSEQ];
__device__ __align__(16) bf16 g_XWH[MR * DMOD], g_XWL[MR * DMOD];
__device__ __align__(16) bf16 g_CATH[MR * DMOD], g_CATL[MR * DMOD];
__device__ float g_L[Bb * NSEQ * NSEQ];

// ---------------- helpers ----------------------------------------------------
__device__ __forceinline__ u32 smem_u32(const void* p) {
    u32 a;
    asm("{ .reg .u64 t; cvta.to.shared.u64 t, %1; cvt.u32.u64 %0, t; }"
        : "=r"(a) : "l"(p));
    return a;
}
__device__ __forceinline__ u32 pack2(bf16 a, bf16 b) {
    __nv_bfloat162 t; t.x = a; t.y = b;
    return *reinterpret_cast<u32*>(&t);
}
__device__ __forceinline__ void split1(float v, bf16& h, bf16& l) {
    h = __float2bfloat16(v);
    l = __float2bfloat16(v - __bfloat162float(h));
}
__device__ __forceinline__ void ldm4(u32 addr, u32& r0, u32& r1, u32& r2, u32& r3) {
    asm volatile("ldmatrix.sync.aligned.m8n8.x4.shared.b16 {%0,%1,%2,%3}, [%4];"
                 : "=r"(r0), "=r"(r1), "=r"(r2), "=r"(r3) : "r"(addr));
}
__device__ __forceinline__ void mma16816(float* c, const u32* a, u32 b0, u32 b1) {
    asm volatile(
        "mma.sync.aligned.m16n8k16.row.col.f32.bf16.bf16.f32 "
        "{%0,%1,%2,%3}, {%4,%5,%6,%7}, {%8,%9}, {%0,%1,%2,%3};"
        : "+f"(c[0]), "+f"(c[1]), "+f"(c[2]), "+f"(c[3])
        : "r"(a[0]), "r"(a[1]), "r"(a[2]), "r"(a[3]), "r"(b0), "r"(b1));
}
__device__ __forceinline__ void cpa16(u32 dst, const void* src) {
    asm volatile("cp.async.cg.shared.global [%0], [%1], 16;"
                 :: "r"(dst), "l"(src) : "memory");
}
__device__ __forceinline__ void cp_commit() {
    asm volatile("cp.async.commit_group;" ::: "memory");
}

// ---------------------------------------------------------------------------
// Split conversion: fp32 -> (hi, lo) bf16 planes.
__global__ void split_f32(const float* __restrict__ in, bf16* __restrict__ hi,
                          bf16* __restrict__ lo, int n4)
{
    int i = blockIdx.x * blockDim.x + threadIdx.x;
    if (i >= n4) return;
    float4 v = ((const float4*)in)[i];
    bf16 h0, h1, h2, h3, l0, l1, l2, l3;
    split1(v.x, h0, l0); split1(v.y, h1, l1);
    split1(v.z, h2, l2); split1(v.w, h3, l3);
    ((uint2*)hi)[i] = make_uint2(pack2(h0, h1), pack2(h2, h3));
    ((uint2*)lo)[i] = make_uint2(pack2(l0, l1), pack2(l2, l3));
}

// Wb [k][n] -> WbT [n][k] split planes
__global__ void transpose_split(const float* __restrict__ in,
                                bf16* __restrict__ oh, bf16* __restrict__ ol)
{
    __shared__ float t[32][33];
    const int tx = threadIdx.x;
    const int x = blockIdx.x * 32 + tx;
    for (int i = threadIdx.y; i < 32; i += 8)
        t[i][tx] = in[(size_t)(blockIdx.y * 32 + i) * DMOD + x];
    __syncthreads();
    const int ox = blockIdx.y * 32 + tx;
    for (int i = threadIdx.y; i < 32; i += 8) {
        bf16 h, l;
        split1(t[tx][i], h, l);
        oh[(size_t)(blockIdx.x * 32 + i) * DMOD + ox] = h;
        ol[(size_t)(blockIdx.x * 32 + i) * DMOD + ox] = l;
    }
}

// ---------------------------------------------------------------------------
// bf16 split GEMM with cp.async double-buffering.
// C[128 x NTILE] = (Ah+Al)[128xK] @ (Bh+Bl)[NTILE x K]^T (3-pass split product)
// EPI: 0 head-scatter -> split planes [z][tok][d] (+bias)
//      2 rowmajor -> split planes
//      3 phrasal: P=sigmoid(acc+bb) fp32 out; aux=lam*log(P+eps)
//      4 logits: 0.125*acc + aux -> fp32
//      6 rowmajor + bias -> fp32
//      7 head-scatter transposed -> split planes [z][d][tok] (+bias)
// ---------------------------------------------------------------------------
template<int NTILE, int EPI>
__global__ __launch_bounds__(256, 1)
void bf_gemm(const bf16* __restrict__ Ah, const bf16* __restrict__ Al,
             const bf16* __restrict__ Bh, const bf16* __restrict__ Bl,
             int K, long long sAz, long long sBz,
             float* __restrict__ out0, float* __restrict__ aux,
             const float* __restrict__ bias,
             const float* __restrict__ s0, const float* __restrict__ s1,
             bf16* __restrict__ oH, bf16* __restrict__ oL)
{
    constexpr int WN  = (NTILE == 128) ? 4 : 2;
    constexpr int WM  = 8 / WN;
    constexpr int MT  = 128 / WM;
    constexpr int NTw = NTILE / WN;
    constexpr int MF  = MT / 16;
    constexpr int NF  = NTw / 8;
    constexpr int PA  = 128 * 128;           // bytes per A plane
    constexpr int PB  = NTILE * 128;
    constexpr int AHI = 0, ALO = PA, BHI = 2 * PA, BLO = 2 * PA + PB;
    constexpr int STAGE = 2 * PA + 2 * PB;

    extern __shared__ char smem[];
    const u32 sb = smem_u32(smem);

    const int tid = threadIdx.x;
    const int wid = tid >> 5, lane = tid & 31;
    const int wM  = wid % WM, wN = wid / WM;
    const int z   = blockIdx.z;
    const int m0  = blockIdx.y * 128;
    const int n0  = blockIdx.x * NTILE;
    const int mat = lane >> 3, lir = lane & 7;
    const int rfr = (mat & 1) * 8 + lir;
    const int kcf = mat >> 1;

    const bf16* Abh = Ah + (size_t)z * sAz + (size_t)m0 * K;
    const bf16* Abl = Al + (size_t)z * sAz + (size_t)m0 * K;
    const bf16* Bbh = Bh + (size_t)z * sBz + (size_t)n0 * K;
    const bf16* Bbl = Bl + (size_t)z * sBz + (size_t)n0 * K;

    float acc[MF][NF][4];
#pragma unroll
    for (int i = 0; i < MF; i++)
#pragma unroll
        for (int j = 0; j < NF; j++)
#pragma unroll
            for (int e = 0; e < 4; e++) acc[i][j][e] = 0.0f;

    const int C = K >> 6;

    auto stage = [&](int c, int s) {
        const int k0 = c << 6;
        const u32 base = sb + (u32)s * STAGE;
#pragma unroll
        for (int u = tid; u < 1024; u += 256) {
            const int row = u >> 3, ch = u & 7;
            const u32 off = (u32)row * 128 + ((((u32)ch ^ ((u32)row & 7))) << 4);
            const size_t so = (size_t)row * K + k0 + ch * 8;
            cpa16(base + AHI + off, Abh + so);
            cpa16(base + ALO + off, Abl + so);
        }
#pragma unroll
        for (int u = tid; u < NTILE * 8; u += 256) {
            const int row = u >> 3, ch = u & 7;
            const u32 off = (u32)row * 128 + ((((u32)ch ^ ((u32)row & 7))) << 4);
            const size_t so = (size_t)row * K + k0 + ch * 8;
            cpa16(base + BHI + off, Bbh + so);
            cpa16(base + BLO + off, Bbl + so);
        }
        cp_commit();
    };

    stage(0, 0);
    for (int c = 0; c < C; c++) {
        if (c + 1 < C) {
            stage(c + 1, (c + 1) & 1);
            asm volatile("cp.async.wait_group 1;" ::: "memory");
        } else {
            asm volatile("cp.async.wait_group 0;" ::: "memory");
        }
        __syncthreads();
        const u32 bb_ = sb + (u32)(c & 1) * STAGE;

#pragma unroll
        for (int ks = 0; ks < 4; ks++) {
            const u32 kch = (u32)(ks * 2 + kcf);
            u32 ah[MF][4], al[MF][4], bx[NF / 2][4];
#pragma unroll
            for (int mi = 0; mi < MF; mi++) {
                const u32 row = (u32)(wM * MT + mi * 16 + rfr);
                const u32 ao  = row * 128 + ((kch ^ (row & 7)) << 4);
                ldm4(bb_ + AHI + ao, ah[mi][0], ah[mi][1], ah[mi][2], ah[mi][3]);
            }
#pragma unroll
            for (int j = 0; j < NF / 2; j++) {
                const u32 row = (u32)(wN * NTw + j * 16 + rfr);
                const u32 bo  = row * 128 + ((kch ^ (row & 7)) << 4);
                ldm4(bb_ + BHI + bo, bx[j][0], bx[j][1], bx[j][2], bx[j][3]);
            }
#pragma unroll
            for (int mi = 0; mi < MF; mi++)
#pragma unroll
                for (int ni = 0; ni < NF; ni++)
                    mma16816(acc[mi][ni], ah[mi],
                             bx[ni >> 1][ni & 1], bx[ni >> 1][(ni & 1) + 2]);
#pragma unroll
            for (int mi = 0; mi < MF; mi++) {
                const u32 row = (u32)(wM * MT + mi * 16 + rfr);
                const u32 ao  = row * 128 + ((kch ^ (row & 7)) << 4);
                ldm4(bb_ + ALO + ao, al[mi][0], al[mi][1], al[mi][2], al[mi][3]);
            }
#pragma unroll
            for (int mi = 0; mi < MF; mi++)
#pragma unroll
                for (int ni = 0; ni < NF; ni++)
                    mma16816(acc[mi][ni], al[mi],
                             bx[ni >> 1][ni & 1], bx[ni >> 1][(ni & 1) + 2]);
#pragma unroll
            for (int j = 0; j < NF / 2; j++) {
                const u32 row = (u32)(wN * NTw + j * 16 + rfr);
                const u32 bo  = row * 128 + ((kch ^ (row & 7)) << 4);
                ldm4(bb_ + BLO + bo, bx[j][0], bx[j][1], bx[j][2], bx[j][3]);
            }
#pragma unroll
            for (int mi = 0; mi < MF; mi++)
#pragma unroll
                for (int ni = 0; ni < NF; ni++)
                    mma16816(acc[mi][ni], ah[mi],
                             bx[ni >> 1][ni & 1], bx[ni >> 1][(ni & 1) + 2]);
        }
        __syncthreads();
    }

    // ---- epilogue ----
    const int gid = lane >> 2, t4 = lane & 3;
#pragma unroll
    for (int mi = 0; mi < MF; mi++) {
#pragma unroll
        for (int h = 0; h < 2; h++) {
            const int m = m0 + wM * MT + mi * 16 + gid + h * 8;
#pragma unroll
            for (int ni = 0; ni < NF; ni++) {
                const int n = n0 + wN * NTw + ni * 8 + t4 * 2;
                float v0 = acc[mi][ni][h * 2 + 0];
                float v1 = acc[mi][ni][h * 2 + 1];

                if (EPI == 0) {
                    const int b = m >> 10, tok = m & 1023;
                    const int hd = n >> 6, d = n & 63;
                    bf16 h0, l0, h1, l1;
                    split1(v0 + bias[n], h0, l0);
                    split1(v1 + bias[n + 1], h1, l1);
                    const size_t ix = (((size_t)(b * Hh + hd) * NSEQ) + tok) * DHd + d;
                    *(u32*)(oH + ix) = pack2(h0, h1);
                    *(u32*)(oL + ix) = pack2(l0, l1);
                } else if (EPI == 7) {
                    const int b = m >> 10, tok = m & 1023;
                    const int hd = n >> 6, d = n & 63;
                    bf16 h0, l0, h1, l1;
                    split1(v0 + bias[n], h0, l0);
                    split1(v1 + bias[n + 1], h1, l1);
                    const size_t zz = (size_t)(b * Hh + hd);
                    oH[(zz * DHd + d) * NSEQ + tok]     = h0;
                    oH[(zz * DHd + d + 1) * NSEQ + tok] = h1;
                    oL[(zz * DHd + d) * NSEQ + tok]     = l0;
                    oL[(zz * DHd + d + 1) * NSEQ + tok] = l1;
                } else if (EPI == 2) {
                    bf16 h0, l0, h1, l1;
                    split1(v0, h0, l0); split1(v1, h1, l1);
                    const size_t ix = (size_t)m * DMOD + n;
                    *(u32*)(oH + ix) = pack2(h0, h1);
                    *(u32*)(oL + ix) = pack2(l0, l1);
                } else if (EPI == 3) {
                    const float bb0 = s0[0], lam = s1[0];
                    float p0 = 1.0f / (1.0f + __expf(-(v0 + bb0)));
                    float p1 = 1.0f / (1.0f + __expf(-(v1 + bb0)));
                    const size_t idx = ((size_t)z * NSEQ + m) * NSEQ + n;
                    *(float2*)(out0 + idx) = make_float2(p0, p1);
                    *(float2*)(aux + idx) =
                        make_float2(lam * __logf(p0 + EPSF), lam * __logf(p1 + EPSF));
                } else if (EPI == 4) {
                    const int bz = z >> 4;
                    const size_t li = ((size_t)bz * NSEQ + m) * NSEQ + n;
                    float2 L = *(const float2*)(aux + li);
                    *(float2*)(out0 + ((size_t)z * NSEQ + m) * NSEQ + n) =
                        make_float2(v0 * 0.125f + L.x, v1 * 0.125f + L.y);
                } else if (EPI == 6) {
                    *(float2*)(out0 + (size_t)m * DMOD + n) =
                        make_float2(v0 + bias[n], v1 + bias[n + 1]);
                }
            }
        }
    }
}

// ---------------------------------------------------------------------------
// AV GEMM: CAT[bz, q, hz*64+d] (split planes) = att[z] @ Vt[z]^T
// A = fp32 att (staged via cp.async, converted smem->smem), B = Vt split planes.
// Block 128x64, K-chunk 64, 16 chunks.
// ---------------------------------------------------------------------------
__global__ __launch_bounds__(256, 1)
void av_gemm(const float* __restrict__ att,
             const bf16* __restrict__ Vth, const bf16* __restrict__ Vtl,
             bf16* __restrict__ oH, bf16* __restrict__ oL)
{
    constexpr int ABH = 65536, ABL = 81920, BB = 98304;
    extern __shared__ char smem[];
    const u32 sb = smem_u32(smem);

    const int tid = threadIdx.x;
    const int wid = tid >> 5, lane = tid & 31;
    const int wM = wid % 4, wN = wid >> 2;       // WM=4, WN=2
    const int z = blockIdx.z, m0 = blockIdx.y * 128;
    const int bz = z >> 4, hz = z & 15;
    const int mat = lane >> 3, lir = lane & 7;
    const int rfr = (mat & 1) * 8 + lir, kcf = mat >> 1;

    const float* Ab = att + (size_t)z * NSEQ * NSEQ + (size_t)m0 * NSEQ;
    const bf16* Bh = Vth + (size_t)z * DHd * NSEQ;
    const bf16* Bl = Vtl + (size_t)z * DHd * NSEQ;

    float acc[2][4][4];
#pragma unroll
    for (int i = 0; i < 2; i++)
#pragma unroll
        for (int j = 0; j < 4; j++)
#pragma unroll
            for (int e = 0; e < 4; e++) acc[i][j][e] = 0.0f;

    auto stage = [&](int c, int s) {
        const int k0 = c << 6;
        const u32 af = sb + (u32)s * 32768;
#pragma unroll
        for (int u = tid; u < 2048; u += 256) {
            const int row = u >> 4, ch = u & 15;
            cpa16(af + (u32)row * 256 + (u32)ch * 16,
                  Ab + (size_t)row * NSEQ + k0 + ch * 4);
        }
        const u32 bbs = sb + BB + (u32)s * 16384;
#pragma unroll
        for (int u = tid; u < 512; u += 256) {
            const int row = u >> 3, ch = u & 7;
            const u32 off = (u32)row * 128 + ((((u32)ch ^ ((u32)row & 7))) << 4);
            const size_t so = (size_t)row * NSEQ + k0 + ch * 8;
            cpa16(bbs + off, Bh + so);
            cpa16(bbs + 8192 + off, Bl + so);
        }
        cp_commit();
    };

    stage(0, 0);
    for (int c = 0; c < 16; c++) {
        if (c < 15) {
            stage(c + 1, (c + 1) & 1);
            asm volatile("cp.async.wait_group 1;" ::: "memory");
        } else {
            asm volatile("cp.async.wait_group 0;" ::: "memory");
        }
        __syncthreads();
        // convert A fp32 -> split bf16
#pragma unroll
        for (int u = tid; u < 2048; u += 256) {
            const int row = u >> 4, q = u & 15;
            float4 v = *(const float4*)(smem + (c & 1) * 32768 + row * 256 + q * 16);
            bf16 h0, h1, h2, h3, l0, l1, l2, l3;
            split1(v.x, h0, l0); split1(v.y, h1, l1);
            split1(v.z, h2, l2); split1(v.w, h3, l3);
            const u32 off = (u32)row * 128 + ((((u32)(q >> 1)) ^ ((u32)row & 7)) << 4)
                          + (u32)(q & 1) * 8;
            *(uint2*)(smem + ABH + off) = make_uint2(pack2(h0, h1), pack2(h2, h3));
            *(uint2*)(smem + ABL + off) = make_uint2(pack2(l0, l1), pack2(l2, l3));
        }
        __syncthreads();

        const u32 bbs = sb + BB + (u32)(c & 1) * 16384;
#pragma unroll
        for (int ks = 0; ks < 4; ks++) {
            const u32 kch = (u32)(ks * 2 + kcf);
            u32 ah[2][4], al[2][4], bx[2][4];
#pragma unroll
            for (int mi = 0; mi < 2; mi++) {
                const u32 row = (u32)(wM * 32 + mi * 16 + rfr);
                const u32 ao  = row * 128 + ((kch ^ (row & 7)) << 4);
                ldm4(sb + ABH + ao, ah[mi][0], ah[mi][1], ah[mi][2], ah[mi][3]);
            }
#pragma unroll
            for (int j = 0; j < 2; j++) {
                const u32 row = (u32)(wN * 32 + j * 16 + rfr);
                const u32 bo  = row * 128 + ((kch ^ (row & 7)) << 4);
                ldm4(bbs + bo, bx[j][0], bx[j][1], bx[j][2], bx[j][3]);
            }
#pragma unroll
            for (int mi = 0; mi < 2; mi++)
#pragma unroll
                for (int ni = 0; ni < 4; ni++)
                    mma16816(acc[mi][ni], ah[mi],
                             bx[ni >> 1][ni & 1], bx[ni >> 1][(ni & 1) + 2]);
#pragma unroll
            for (int mi = 0; mi < 2; mi++) {
                const u32 row = (u32)(wM * 32 + mi * 16 + rfr);
                const u32 ao  = row * 128 + ((kch ^ (row & 7)) << 4);
                ldm4(sb + ABL + ao, al[mi][0], al[mi][1], al[mi][2], al[mi][3]);
            }
#pragma unroll
            for (int mi = 0; mi < 2; mi++)
#pragma unroll
                for (int ni = 0; ni < 4; ni++)
                    mma16816(acc[mi][ni], al[mi],
                             bx[ni >> 1][ni & 1], bx[ni >> 1][(ni & 1) + 2]);
#pragma unroll
            for (int j = 0; j < 2; j++) {
                const u32 row = (u32)(wN * 32 + j * 16 + rfr);
                const u32 bo  = row * 128 + ((kch ^ (row & 7)) << 4);
                ldm4(bbs + 8192 + bo, bx[j][0], bx[j][1], bx[j][2], bx[j][3]);
            }
#pragma unroll
            for (int mi = 0; mi < 2; mi++)
#pragma unroll
                for (int ni = 0; ni < 4; ni++)
                    mma16816(acc[mi][ni], ah[mi],
                             bx[ni >> 1][ni & 1], bx[ni >> 1][(ni & 1) + 2]);
        }
        __syncthreads();
    }

    const int gid = lane >> 2, t4 = lane & 3;
#pragma unroll
    for (int mi = 0; mi < 2; mi++) {
#pragma unroll
        for (int h = 0; h < 2; h++) {
            const int m = m0 + wM * 32 + mi * 16 + gid + h * 8;
#pragma unroll
            for (int ni = 0; ni < 4; ni++) {
                const int n = wN * 32 + ni * 8 + t4 * 2;
                bf16 h0, l0, h1, l1;
                split1(acc[mi][ni][h * 2 + 0], h0, l0);
                split1(acc[mi][ni][h * 2 + 1], h1, l1);
                const size_t ix = ((size_t)bz * NSEQ + m) * DMOD + hz * DHd + n;
                *(u32*)(oH + ix) = pack2(h0, h1);
                *(u32*)(oL + ix) = pack2(l0, l1);
            }
        }
    }
}

// ---------------------------------------------------------------------------
__global__ __launch_bounds__(256)
void softmax_rows(float* __restrict__ att)
{
    const size_t row = (size_t)blockIdx.x * 8 + (threadIdx.x >> 5);
    const int lane = threadIdx.x & 31;
    float4* p4 = (float4*)(att + row * 1024);
    float4 v[8];
    float mx = -3.4e38f;
#pragma unroll
    for (int i = 0; i < 8; i++) {
        v[i] = p4[lane + 32 * i];
        mx = fmaxf(mx, fmaxf(fmaxf(v[i].x, v[i].y), fmaxf(v[i].z, v[i].w)));
    }
#pragma unroll
    for (int o = 16; o > 0; o >>= 1)
        mx = fmaxf(mx, __shfl_xor_sync(0xffffffffu, mx, o));
    float s = 0.0f;
#pragma unroll
    for (int i = 0; i < 8; i++) {
        v[i].x = __expf(v[i].x - mx); v[i].y = __expf(v[i].y - mx);
        v[i].z = __expf(v[i].z - mx); v[i].w = __expf(v[i].w - mx);
        s += v[i].x + v[i].y + v[i].z + v[i].w;
    }
#pragma unroll
    for (int o = 16; o > 0; o >>= 1)
        s += __shfl_xor_sync(0xffffffffu, s, o);
    const float inv = 1.0f / s;
#pragma unroll
    for (int i = 0; i < 8; i++) {
        v[i].x *= inv; v[i].y *= inv; v[i].z *= inv; v[i].w *= inv;
        p4[lane + 32 * i] = v[i];
    }
}

// ---------------------------------------------------------------------------
extern "C" void kernel_launch(void* const* d_in, const int* in_sizes, int n_in,
                              void* d_out, int out_size)
{
    const float* queries = (const float*)d_in[0];
    const float* keys    = (const float*)d_in[1];
    const float* values  = (const float*)d_in[2];
    const float* Wq = (const float*)d_in[3];  const float* bq = (const float*)d_in[4];
    const float* Wk = (const float*)d_in[5];  const float* bk = (const float*)d_in[6];
    const float* Wv = (const float*)d_in[7];  const float* bv = (const float*)d_in[8];
    const float* Wo = (const float*)d_in[9];  const float* bo = (const float*)d_in[10];
    const float* Wb = (const float*)d_in[11]; const float* bb = (const float*)d_in[12];
    const float* lam = (const float*)d_in[13];

    float* out_main = (float*)d_out;
    float* att      = out_main + (size_t)Bb * NSEQ * DMOD;
    float* Pout     = att + (size_t)Bb * Hh * NSEQ * NSEQ;

#define GA(sym, var) bf16* var; cudaGetSymbolAddress((void**)&var, sym)
    GA(g_qsH, qsH); GA(g_qsL, qsL); GA(g_ksH, ksH); GA(g_ksL, ksL);
    GA(g_vsH, vsH); GA(g_vsL, vsL);
    GA(g_WqH, WqH); GA(g_WqL, WqL); GA(g_WkH, WkH); GA(g_WkL, WkL);
    GA(g_WvH, WvH); GA(g_WvL, WvL); GA(g_WoH, WoH); GA(g_WoL, WoL);
    GA(g_WbTH, WbTH); GA(g_WbTL, WbTL);
    GA(g_QH, QH); GA(g_QL, QL); GA(g_KH, KH); GA(g_KL, KL);
    GA(g_VtH, VtH); GA(g_VtL, VtL);
    GA(g_XWH, XWH); GA(g_XWL, XWL);
    GA(g_CATH, CATH); GA(g_CATL, CATL);
#undef GA
    float* gL; cudaGetSymbolAddress((void**)&gL, g_L);

    const int SM2 = 131072;   // two-stage pipeline
    const int SM1 = 65536;    // single chunk (logits)
    cudaFuncSetAttribute(bf_gemm<128,0>, cudaFuncAttributeMaxDynamicSharedMemorySize, SM2);
    cudaFuncSetAttribute(bf_gemm<128,2>, cudaFuncAttributeMaxDynamicSharedMemorySize, SM2);
    cudaFuncSetAttribute(bf_gemm<128,3>, cudaFuncAttributeMaxDynamicSharedMemorySize, SM2);
    cudaFuncSetAttribute(bf_gemm<128,4>, cudaFuncAttributeMaxDynamicSharedMemorySize, SM1);
    cudaFuncSetAttribute(bf_gemm<128,6>, cudaFuncAttributeMaxDynamicSharedMemorySize, SM2);
    cudaFuncSetAttribute(bf_gemm<128,7>, cudaFuncAttributeMaxDynamicSharedMemorySize, SM2);
    cudaFuncSetAttribute(av_gemm,        cudaFuncAttributeMaxDynamicSharedMemorySize, SM2);

    // ---- conversions ----
    const int n4in = MR * DMOD / 4;
    split_f32<<<n4in / 256, 256>>>(queries, qsH, qsL, n4in);
    split_f32<<<n4in / 256, 256>>>(keys,    ksH, ksL, n4in);
    split_f32<<<n4in / 256, 256>>>(values,  vsH, vsL, n4in);
    const int n4w = DMOD * DMOD / 4;
    split_f32<<<n4w / 256, 256>>>(Wq, WqH, WqL, n4w);
    split_f32<<<n4w / 256, 256>>>(Wk, WkH, WkL, n4w);
    split_f32<<<n4w / 256, 256>>>(Wv, WvH, WvL, n4w);
    split_f32<<<n4w / 256, 256>>>(Wo, WoH, WoL, n4w);
    transpose_split<<<dim3(32, 32), dim3(32, 8)>>>(Wb, WbTH, WbTL);

    dim3 blk(256);
    dim3 gP(DMOD / 128, MR / 128, 1);   // 8 x 64

    // projections
    bf_gemm<128,0><<<gP, blk, SM2>>>(qsH, qsL, WqH, WqL, DMOD, 0, 0,
                                     nullptr, nullptr, bq, nullptr, nullptr, QH, QL);
    bf_gemm<128,0><<<gP, blk, SM2>>>(ksH, ksL, WkH, WkL, DMOD, 0, 0,
                                     nullptr, nullptr, bk, nullptr, nullptr, KH, KL);
    bf_gemm<128,7><<<gP, blk, SM2>>>(vsH, vsL, WvH, WvL, DMOD, 0, 0,
                                     nullptr, nullptr, bv, nullptr, nullptr, VtH, VtL);
    // xW
    bf_gemm<128,2><<<gP, blk, SM2>>>(qsH, qsL, WbTH, WbTL, DMOD, 0, 0,
                                     nullptr, nullptr, nullptr, nullptr, nullptr, XWH, XWL);
    // P + L
    bf_gemm<128,3><<<dim3(8, 8, Bb), blk, SM2>>>(
        XWH, XWL, qsH, qsL, DMOD,
        (long long)NSEQ * DMOD, (long long)NSEQ * DMOD,
        Pout, gL, nullptr, bb, lam, nullptr, nullptr);
    // logits (K=64, single chunk -> 64KB smem, 2 CTAs/SM)
    bf_gemm<128,4><<<dim3(8, 8, Bb * Hh), blk, SM1>>>(
        QH, QL, KH, KL, DHd,
        (long long)NSEQ * DHd, (long long)NSEQ * DHd,
        att, gL, nullptr, nullptr, nullptr, nullptr, nullptr);
    // softmax in place
    softmax_rows<<<(Bb * Hh * NSEQ) / 8, 256>>>(att);
    // CAT = att @ V
    av_gemm<<<dim3(1, 8, Bb * Hh), blk, SM2>>>(att, VtH, VtL, CATH, CATL);
    // out = CAT @ Wo^T + bo
    bf_gemm<128,6><<<gP, blk, SM2>>>(CATH, CATL, WoH, WoL, DMOD, 0, 0,
                                     out_main, nullptr, bo, nullptr, nullptr,
                                     nullptr, nullptr);

    (void)in_sizes; (void)n_in; (void)out_size;
}

// round 6
// speedup vs baseline: 1.6071x; 1.6071x over previous
#include <cuda_runtime.h>
#include <cuda_bf16.h>
#include <stdint.h>
#include <math.h>

#define Bb    8
#define Hh    16
#define NSEQ  1024
#define DMOD  1024
#define DHd   64
#define MR    (Bb * NSEQ)
#define EPSF  1e-9f

typedef unsigned int u32;
typedef unsigned long long u64;
typedef __nv_bfloat16 bf16;

// ---------------- scratch (device globals; allocations forbidden) -----------
__device__ __align__(16) bf16 g_qsH[MR * DMOD], g_qsL[MR * DMOD];
__device__ __align__(16) bf16 g_ksH[MR * DMOD], g_ksL[MR * DMOD];
__device__ __align__(16) bf16 g_vsH[MR * DMOD], g_vsL[MR * DMOD];
__device__ __align__(16) bf16 g_WqH[DMOD * DMOD], g_WqL[DMOD * DMOD];
__device__ __align__(16) bf16 g_WkH[DMOD * DMOD], g_WkL[DMOD * DMOD];
__device__ __align__(16) bf16 g_WvH[DMOD * DMOD], g_WvL[DMOD * DMOD];
__device__ __align__(16) bf16 g_WoH[DMOD * DMOD], g_WoL[DMOD * DMOD];
__device__ __align__(16) bf16 g_WbTH[DMOD * DMOD], g_WbTL[DMOD * DMOD];
__device__ __align__(16) bf16 g_QH[MR * DMOD], g_QL[MR * DMOD];
__device__ __align__(16) bf16 g_KH[MR * DMOD], g_KL[MR * DMOD];
__device__ __align__(16) bf16 g_VtH[MR * DMOD], g_VtL[MR * DMOD];
__device__ __align__(16) bf16 g_XWH[MR * DMOD], g_XWL[MR * DMOD];
__device__ __align__(16) bf16 g_CATH[MR * DMOD], g_CATL[MR * DMOD];
__device__ float g_L[Bb * NSEQ * NSEQ];

// ---------------- helpers ----------------------------------------------------
__device__ __forceinline__ u32 smem_u32(const void* p) {
    u32 a;
    asm("{ .reg .u64 t; cvta.to.shared.u64 t, %1; cvt.u32.u64 %0, t; }"
        : "=r"(a) : "l"(p));
    return a;
}
__device__ __forceinline__ u32 pack2(bf16 a, bf16 b) {
    __nv_bfloat162 t; t.x = a; t.y = b;
    return *reinterpret_cast<u32*>(&t);
}
__device__ __forceinline__ void split1(float v, bf16& h, bf16& l) {
    h = __float2bfloat16(v);
    l = __float2bfloat16(v - __bfloat162float(h));
}
__device__ __forceinline__ void ldm4(u32 addr, u32& r0, u32& r1, u32& r2, u32& r3) {
    asm volatile("ldmatrix.sync.aligned.m8n8.x4.shared.b16 {%0,%1,%2,%3}, [%4];"
                 : "=r"(r0), "=r"(r1), "=r"(r2), "=r"(r3) : "r"(addr));
}
__device__ __forceinline__ void mma16816(float* c, const u32* a, u32 b0, u32 b1) {
    asm volatile(
        "mma.sync.aligned.m16n8k16.row.col.f32.bf16.bf16.f32 "
        "{%0,%1,%2,%3}, {%4,%5,%6,%7}, {%8,%9}, {%0,%1,%2,%3};"
        : "+f"(c[0]), "+f"(c[1]), "+f"(c[2]), "+f"(c[3])
        : "r"(a[0]), "r"(a[1]), "r"(a[2]), "r"(a[3]), "r"(b0), "r"(b1));
}
__device__ __forceinline__ void cpa16(u32 dst, const void* src) {
    asm volatile("cp.async.cg.shared.global [%0], [%1], 16;"
                 :: "r"(dst), "l"(src) : "memory");
}
__device__ __forceinline__ void cp_commit() {
    asm volatile("cp.async.commit_group;" ::: "memory");
}
// swizzled offset for 64B rows (4x16B chunks)
__device__ __forceinline__ u32 swz64(u32 row, u32 ch) {
    return row * 64u + ((ch ^ ((row >> 1) & 3u)) << 4);
}

// ---------------------------------------------------------------------------
__global__ void split_f32(const float* __restrict__ in, bf16* __restrict__ hi,
                          bf16* __restrict__ lo, int n4)
{
    int i = blockIdx.x * blockDim.x + threadIdx.x;
    if (i >= n4) return;
    float4 v = ((const float4*)in)[i];
    bf16 h0, h1, h2, h3, l0, l1, l2, l3;
    split1(v.x, h0, l0); split1(v.y, h1, l1);
    split1(v.z, h2, l2); split1(v.w, h3, l3);
    ((uint2*)hi)[i] = make_uint2(pack2(h0, h1), pack2(h2, h3));
    ((uint2*)lo)[i] = make_uint2(pack2(l0, l1), pack2(l2, l3));
}

__global__ void transpose_split(const float* __restrict__ in,
                                bf16* __restrict__ oh, bf16* __restrict__ ol)
{
    __shared__ float t[32][33];
    const int tx = threadIdx.x;
    const int x = blockIdx.x * 32 + tx;
    for (int i = threadIdx.y; i < 32; i += 8)
        t[i][tx] = in[(size_t)(blockIdx.y * 32 + i) * DMOD + x];
    __syncthreads();
    const int ox = blockIdx.y * 32 + tx;
    for (int i = threadIdx.y; i < 32; i += 8) {
        bf16 h, l;
        split1(t[tx][i], h, l);
        oh[(size_t)(blockIdx.x * 32 + i) * DMOD + ox] = h;
        ol[(size_t)(blockIdx.x * 32 + i) * DMOD + ox] = l;
    }
}

// ---------------------------------------------------------------------------
// Split-plane bf16 GEMM, K-chunk 32, 2-stage cp.async pipeline, 64KB smem,
// 2 CTAs/SM. C[128x128] = (Ah+Al) @ (Bh+Bl)^T, NT layout.
// EPI: 0 head-scatter planes [z][tok][d] (+bias)
//      2 rowmajor planes
//      3 phrasal: P=sigmoid(acc+bb) fp32; aux=lam*log(P+eps)
//      4 logits: 0.125*acc + aux -> fp32
//      6 rowmajor + bias -> fp32
//      7 head-scatter transposed planes [z][d][tok] (+bias)
// ---------------------------------------------------------------------------
template<int EPI>
__global__ __launch_bounds__(256, 2)
void bf_gemm(const bf16* __restrict__ Ah, const bf16* __restrict__ Al,
             const bf16* __restrict__ Bh, const bf16* __restrict__ Bl,
             int K, long long sAz, long long sBz,
             float* __restrict__ out0, float* __restrict__ aux,
             const float* __restrict__ bias,
             const float* __restrict__ s0, const float* __restrict__ s1,
             bf16* __restrict__ oH, bf16* __restrict__ oL)
{
    constexpr int PA = 128 * 64;                    // 8KB per plane per stage
    constexpr int AHI = 0, ALO = PA, BHI = 2 * PA, BLO = 3 * PA;
    constexpr int STAGE = 4 * PA;                   // 32KB

    extern __shared__ char smem[];
    const u32 sb = smem_u32(smem);

    const int tid = threadIdx.x;
    const int wid = tid >> 5, lane = tid & 31;
    const int wM = wid & 1, wN = wid >> 1;          // WM=2, WN=4
    const int z  = blockIdx.z;
    const int m0 = blockIdx.y * 128;
    const int n0 = blockIdx.x * 128;
    const int mat = lane >> 3, lir = lane & 7;
    const int rfr = (mat & 1) * 8 + lir;
    const int kcf = mat >> 1;

    const bf16* Abh = Ah + (size_t)z * sAz + (size_t)m0 * K;
    const bf16* Abl = Al + (size_t)z * sAz + (size_t)m0 * K;
    const bf16* Bbh = Bh + (size_t)z * sBz + (size_t)n0 * K;
    const bf16* Bbl = Bl + (size_t)z * sBz + (size_t)n0 * K;

    float acc[4][4][4];
#pragma unroll
    for (int i = 0; i < 4; i++)
#pragma unroll
        for (int j = 0; j < 4; j++)
#pragma unroll
            for (int e = 0; e < 4; e++) acc[i][j][e] = 0.0f;

    const int C = K >> 5;

    auto stage = [&](int c, int s) {
        const int k0 = c << 5;
        const u32 base = sb + (u32)s * STAGE;
#pragma unroll
        for (int u = tid; u < 512; u += 256) {
            const u32 row = (u32)(u >> 2), ch = (u32)(u & 3);
            const u32 off = swz64(row, ch);
            const size_t so = (size_t)row * K + k0 + ch * 8;
            cpa16(base + AHI + off, Abh + so);
            cpa16(base + ALO + off, Abl + so);
            cpa16(base + BHI + off, Bbh + so);
            cpa16(base + BLO + off, Bbl + so);
        }
        cp_commit();
    };

    stage(0, 0);
    for (int c = 0; c < C; c++) {
        if (c + 1 < C) {
            stage(c + 1, (c + 1) & 1);
            asm volatile("cp.async.wait_group 1;" ::: "memory");
        } else {
            asm volatile("cp.async.wait_group 0;" ::: "memory");
        }
        __syncthreads();
        const u32 bbase = sb + (u32)(c & 1) * STAGE;

#pragma unroll
        for (int ks = 0; ks < 2; ks++) {
            const u32 kch = (u32)(ks * 2 + kcf);
            u32 ah[4][4], al[4][4], bx[2][4];
#pragma unroll
            for (int mi = 0; mi < 4; mi++) {
                const u32 row = (u32)(wM * 64 + mi * 16 + rfr);
                ldm4(bbase + AHI + swz64(row, kch),
                     ah[mi][0], ah[mi][1], ah[mi][2], ah[mi][3]);
            }
#pragma unroll
            for (int j = 0; j < 2; j++) {
                const u32 row = (u32)(wN * 32 + j * 16 + rfr);
                ldm4(bbase + BHI + swz64(row, kch),
                     bx[j][0], bx[j][1], bx[j][2], bx[j][3]);
            }
#pragma unroll
            for (int mi = 0; mi < 4; mi++)
#pragma unroll
                for (int ni = 0; ni < 4; ni++)
                    mma16816(acc[mi][ni], ah[mi],
                             bx[ni >> 1][ni & 1], bx[ni >> 1][(ni & 1) + 2]);
#pragma unroll
            for (int mi = 0; mi < 4; mi++) {
                const u32 row = (u32)(wM * 64 + mi * 16 + rfr);
                ldm4(bbase + ALO + swz64(row, kch),
                     al[mi][0], al[mi][1], al[mi][2], al[mi][3]);
            }
#pragma unroll
            for (int mi = 0; mi < 4; mi++)
#pragma unroll
                for (int ni = 0; ni < 4; ni++)
                    mma16816(acc[mi][ni], al[mi],
                             bx[ni >> 1][ni & 1], bx[ni >> 1][(ni & 1) + 2]);
#pragma unroll
            for (int j = 0; j < 2; j++) {
                const u32 row = (u32)(wN * 32 + j * 16 + rfr);
                ldm4(bbase + BLO + swz64(row, kch),
                     bx[j][0], bx[j][1], bx[j][2], bx[j][3]);
            }
#pragma unroll
            for (int mi = 0; mi < 4; mi++)
#pragma unroll
                for (int ni = 0; ni < 4; ni++)
                    mma16816(acc[mi][ni], ah[mi],
                             bx[ni >> 1][ni & 1], bx[ni >> 1][(ni & 1) + 2]);
        }
        __syncthreads();
    }

    // ---- epilogue ----
    const int gid = lane >> 2, t4 = lane & 3;
#pragma unroll
    for (int mi = 0; mi < 4; mi++) {
#pragma unroll
        for (int h = 0; h < 2; h++) {
            const int m = m0 + wM * 64 + mi * 16 + gid + h * 8;
#pragma unroll
            for (int ni = 0; ni < 4; ni++) {
                const int n = n0 + wN * 32 + ni * 8 + t4 * 2;
                float v0 = acc[mi][ni][h * 2 + 0];
                float v1 = acc[mi][ni][h * 2 + 1];

                if (EPI == 0) {
                    const int b = m >> 10, tok = m & 1023;
                    const int hd = n >> 6, d = n & 63;
                    bf16 h0, l0, h1, l1;
                    split1(v0 + bias[n], h0, l0);
                    split1(v1 + bias[n + 1], h1, l1);
                    const size_t ix = (((size_t)(b * Hh + hd) * NSEQ) + tok) * DHd + d;
                    *(u32*)(oH + ix) = pack2(h0, h1);
                    *(u32*)(oL + ix) = pack2(l0, l1);
                } else if (EPI == 7) {
                    const int b = m >> 10, tok = m & 1023;
                    const int hd = n >> 6, d = n & 63;
                    bf16 h0, l0, h1, l1;
                    split1(v0 + bias[n], h0, l0);
                    split1(v1 + bias[n + 1], h1, l1);
                    const size_t zz = (size_t)(b * Hh + hd);
                    oH[(zz * DHd + d) * NSEQ + tok]     = h0;
                    oH[(zz * DHd + d + 1) * NSEQ + tok] = h1;
                    oL[(zz * DHd + d) * NSEQ + tok]     = l0;
                    oL[(zz * DHd + d + 1) * NSEQ + tok] = l1;
                } else if (EPI == 2) {
                    bf16 h0, l0, h1, l1;
                    split1(v0, h0, l0); split1(v1, h1, l1);
                    const size_t ix = (size_t)m * DMOD + n;
                    *(u32*)(oH + ix) = pack2(h0, h1);
                    *(u32*)(oL + ix) = pack2(l0, l1);
                } else if (EPI == 3) {
                    const float bb0 = s0[0], lam = s1[0];
                    float p0 = 1.0f / (1.0f + __expf(-(v0 + bb0)));
                    float p1 = 1.0f / (1.0f + __expf(-(v1 + bb0)));
                    const size_t idx = ((size_t)z * NSEQ + m) * NSEQ + n;
                    *(float2*)(out0 + idx) = make_float2(p0, p1);
                    *(float2*)(aux + idx) =
                        make_float2(lam * __logf(p0 + EPSF), lam * __logf(p1 + EPSF));
                } else if (EPI == 4) {
                    const int bz = z >> 4;
                    const size_t li = ((size_t)bz * NSEQ + m) * NSEQ + n;
                    float2 L = *(const float2*)(aux + li);
                    *(float2*)(out0 + ((size_t)z * NSEQ + m) * NSEQ + n) =
                        make_float2(v0 * 0.125f + L.x, v1 * 0.125f + L.y);
                } else if (EPI == 6) {
                    *(float2*)(out0 + (size_t)m * DMOD + n) =
                        make_float2(v0 + bias[n], v1 + bias[n + 1]);
                }
            }
        }
    }
}

// ---------------------------------------------------------------------------
// AV GEMM: CAT planes = att(fp32) @ Vt^T. Block 128x64, K-chunk 32, 2-stage,
// 64KB smem -> 2 CTAs/SM. A converted fp32->planes in smem.
// smem: [0,32K) A raw stages; [32K,48K) B stages (HI+LO 4KB each);
//       [48K,56K) conv AH; [56K,64K) conv AL
// ---------------------------------------------------------------------------
__global__ __launch_bounds__(256, 2)
void av_gemm(const float* __restrict__ att,
             const bf16* __restrict__ Vth, const bf16* __restrict__ Vtl,
             bf16* __restrict__ oH, bf16* __restrict__ oL)
{
    constexpr int S_B = 32768, S_CH = 49152, S_CL = 57344;
    extern __shared__ char smem[];
    const u32 sb = smem_u32(smem);

    const int tid = threadIdx.x;
    const int wid = tid >> 5, lane = tid & 31;
    const int wM = wid & 3, wN = wid >> 2;          // WM=4, WN=2
    const int z = blockIdx.z, m0 = blockIdx.y * 128;
    const int bz = z >> 4, hz = z & 15;
    const int mat = lane >> 3, lir = lane & 7;
    const int rfr = (mat & 1) * 8 + lir, kcf = mat >> 1;

    const float* Ab = att + (size_t)z * NSEQ * NSEQ + (size_t)m0 * NSEQ;
    const bf16* Bh = Vth + (size_t)z * DHd * NSEQ;
    const bf16* Bl = Vtl + (size_t)z * DHd * NSEQ;

    float acc[2][4][4];
#pragma unroll
    for (int i = 0; i < 2; i++)
#pragma unroll
        for (int j = 0; j < 4; j++)
#pragma unroll
            for (int e = 0; e < 4; e++) acc[i][j][e] = 0.0f;

    auto stage = [&](int c, int s) {
        const int k0 = c << 5;
        const u32 araw = sb + (u32)s * 16384;
#pragma unroll
        for (int u = tid; u < 1024; u += 256) {
            const u32 row = (u32)(u >> 3), ch = (u32)(u & 7);
            cpa16(araw + row * 128 + ch * 16, Ab + (size_t)row * NSEQ + k0 + ch * 4);
        }
        const u32 bbs = sb + S_B + (u32)s * 8192;
#pragma unroll
        for (int u = tid; u < 256; u += 256) {
            const u32 row = (u32)(u >> 2), ch = (u32)(u & 3);
            const u32 off = swz64(row, ch);
            const size_t so = (size_t)row * NSEQ + k0 + ch * 8;
            cpa16(bbs + off, Bh + so);
            cpa16(bbs + 4096 + off, Bl + so);
        }
        cp_commit();
    };

    stage(0, 0);
    for (int c = 0; c < 32; c++) {
        if (c < 31) {
            stage(c + 1, (c + 1) & 1);
            asm volatile("cp.async.wait_group 1;" ::: "memory");
        } else {
            asm volatile("cp.async.wait_group 0;" ::: "memory");
        }
        __syncthreads();
        // convert A fp32 -> split planes
        const char* araw = smem + (c & 1) * 16384;
#pragma unroll
        for (int u = tid; u < 1024; u += 256) {
            const u32 row = (u32)(u >> 3), q = (u32)(u & 7);
            float4 v = *(const float4*)(araw + row * 128 + q * 16);
            bf16 h0, h1, h2, h3, l0, l1, l2, l3;
            split1(v.x, h0, l0); split1(v.y, h1, l1);
            split1(v.z, h2, l2); split1(v.w, h3, l3);
            const u32 off = swz64(row, q >> 1) + (q & 1) * 8;
            *(uint2*)(smem + S_CH + off) = make_uint2(pack2(h0, h1), pack2(h2, h3));
            *(uint2*)(smem + S_CL + off) = make_uint2(pack2(l0, l1), pack2(l2, l3));
        }
        __syncthreads();

        const u32 bbs = sb + S_B + (u32)(c & 1) * 8192;
#pragma unroll
        for (int ks = 0; ks < 2; ks++) {
            const u32 kch = (u32)(ks * 2 + kcf);
            u32 ah[2][4], al[2][4], bx[2][4];
#pragma unroll
            for (int mi = 0; mi < 2; mi++) {
                const u32 row = (u32)(wM * 32 + mi * 16 + rfr);
                ldm4(sb + S_CH + swz64(row, kch),
                     ah[mi][0], ah[mi][1], ah[mi][2], ah[mi][3]);
            }
#pragma unroll
            for (int j = 0; j < 2; j++) {
                const u32 row = (u32)(wN * 32 + j * 16 + rfr);
                ldm4(bbs + swz64(row, kch), bx[j][0], bx[j][1], bx[j][2], bx[j][3]);
            }
#pragma unroll
            for (int mi = 0; mi < 2; mi++)
#pragma unroll
                for (int ni = 0; ni < 4; ni++)
                    mma16816(acc[mi][ni], ah[mi],
                             bx[ni >> 1][ni & 1], bx[ni >> 1][(ni & 1) + 2]);
#pragma unroll
            for (int mi = 0; mi < 2; mi++) {
                const u32 row = (u32)(wM * 32 + mi * 16 + rfr);
                ldm4(sb + S_CL + swz64(row, kch),
                     al[mi][0], al[mi][1], al[mi][2], al[mi][3]);
            }
#pragma unroll
            for (int mi = 0; mi < 2; mi++)
#pragma unroll
                for (int ni = 0; ni < 4; ni++)
                    mma16816(acc[mi][ni], al[mi],
                             bx[ni >> 1][ni & 1], bx[ni >> 1][(ni & 1) + 2]);
#pragma unroll
            for (int j = 0; j < 2; j++) {
                const u32 row = (u32)(wN * 32 + j * 16 + rfr);
                ldm4(bbs + 4096 + swz64(row, kch),
                     bx[j][0], bx[j][1], bx[j][2], bx[j][3]);
            }
#pragma unroll
            for (int mi = 0; mi < 2; mi++)
#pragma unroll
                for (int ni = 0; ni < 4; ni++)
                    mma16816(acc[mi][ni], ah[mi],
                             bx[ni >> 1][ni & 1], bx[ni >> 1][(ni & 1) + 2]);
        }
        __syncthreads();
    }

    const int gid = lane >> 2, t4 = lane & 3;
#pragma unroll
    for (int mi = 0; mi < 2; mi++) {
#pragma unroll
        for (int h = 0; h < 2; h++) {
            const int m = m0 + wM * 32 + mi * 16 + gid + h * 8;
#pragma unroll
            for (int ni = 0; ni < 4; ni++) {
                const int n = wN * 32 + ni * 8 + t4 * 2;
                bf16 h0, l0, h1, l1;
                split1(acc[mi][ni][h * 2 + 0], h0, l0);
                split1(acc[mi][ni][h * 2 + 1], h1, l1);
                const size_t ix = ((size_t)bz * NSEQ + m) * DMOD + hz * DHd + n;
                *(u32*)(oH + ix) = pack2(h0, h1);
                *(u32*)(oL + ix) = pack2(l0, l1);
            }
        }
    }
}

// ---------------------------------------------------------------------------
__global__ __launch_bounds__(256)
void softmax_rows(float* __restrict__ att)
{
    const size_t row = (size_t)blockIdx.x * 8 + (threadIdx.x >> 5);
    const int lane = threadIdx.x & 31;
    float4* p4 = (float4*)(att + row * 1024);
    float4 v[8];
    float mx = -3.4e38f;
#pragma unroll
    for (int i = 0; i < 8; i++) {
        v[i] = p4[lane + 32 * i];
        mx = fmaxf(mx, fmaxf(fmaxf(v[i].x, v[i].y), fmaxf(v[i].z, v[i].w)));
    }
#pragma unroll
    for (int o = 16; o > 0; o >>= 1)
        mx = fmaxf(mx, __shfl_xor_sync(0xffffffffu, mx, o));
    float s = 0.0f;
#pragma unroll
    for (int i = 0; i < 8; i++) {
        v[i].x = __expf(v[i].x - mx); v[i].y = __expf(v[i].y - mx);
        v[i].z = __expf(v[i].z - mx); v[i].w = __expf(v[i].w - mx);
        s += v[i].x + v[i].y + v[i].z + v[i].w;
    }
#pragma unroll
    for (int o = 16; o > 0; o >>= 1)
        s += __shfl_xor_sync(0xffffffffu, s, o);
    const float inv = 1.0f / s;
#pragma unroll
    for (int i = 0; i < 8; i++) {
        v[i].x *= inv; v[i].y *= inv; v[i].z *= inv; v[i].w *= inv;
        p4[lane + 32 * i] = v[i];
    }
}

// ---------------------------------------------------------------------------
extern "C" void kernel_launch(void* const* d_in, const int* in_sizes, int n_in,
                              void* d_out, int out_size)
{
    const float* queries = (const float*)d_in[0];
    const float* keys    = (const float*)d_in[1];
    const float* values  = (const float*)d_in[2];
    const float* Wq = (const float*)d_in[3];  const float* bq = (const float*)d_in[4];
    const float* Wk = (const float*)d_in[5];  const float* bk = (const float*)d_in[6];
    const float* Wv = (const float*)d_in[7];  const float* bv = (const float*)d_in[8];
    const float* Wo = (const float*)d_in[9];  const float* bo = (const float*)d_in[10];
    const float* Wb = (const float*)d_in[11]; const float* bb = (const float*)d_in[12];
    const float* lam = (const float*)d_in[13];

    float* out_main = (float*)d_out;
    float* att      = out_main + (size_t)Bb * NSEQ * DMOD;
    float* Pout     = att + (size_t)Bb * Hh * NSEQ * NSEQ;

#define GA(sym, var) bf16* var; cudaGetSymbolAddress((void**)&var, sym)
    GA(g_qsH, qsH); GA(g_qsL, qsL); GA(g_ksH, ksH); GA(g_ksL, ksL);
    GA(g_vsH, vsH); GA(g_vsL, vsL);
    GA(g_WqH, WqH); GA(g_WqL, WqL); GA(g_WkH, WkH); GA(g_WkL, WkL);
    GA(g_WvH, WvH); GA(g_WvL, WvL); GA(g_WoH, WoH); GA(g_WoL, WoL);
    GA(g_WbTH, WbTH); GA(g_WbTL, WbTL);
    GA(g_QH, QH); GA(g_QL, QL); GA(g_KH, KH); GA(g_KL, KL);
    GA(g_VtH, VtH); GA(g_VtL, VtL);
    GA(g_XWH, XWH); GA(g_XWL, XWL);
    GA(g_CATH, CATH); GA(g_CATL, CATL);
#undef GA
    float* gL; cudaGetSymbolAddress((void**)&gL, g_L);

    const int SM = 65536;
    cudaFuncSetAttribute(bf_gemm<0>, cudaFuncAttributeMaxDynamicSharedMemorySize, SM);
    cudaFuncSetAttribute(bf_gemm<2>, cudaFuncAttributeMaxDynamicSharedMemorySize, SM);
    cudaFuncSetAttribute(bf_gemm<3>, cudaFuncAttributeMaxDynamicSharedMemorySize, SM);
    cudaFuncSetAttribute(bf_gemm<4>, cudaFuncAttributeMaxDynamicSharedMemorySize, SM);
    cudaFuncSetAttribute(bf_gemm<6>, cudaFuncAttributeMaxDynamicSharedMemorySize, SM);
    cudaFuncSetAttribute(bf_gemm<7>, cudaFuncAttributeMaxDynamicSharedMemorySize, SM);
    cudaFuncSetAttribute(av_gemm,    cudaFuncAttributeMaxDynamicSharedMemorySize, SM);

    // ---- one-shot conversions ----
    const int n4in = MR * DMOD / 4;
    split_f32<<<n4in / 256, 256>>>(queries, qsH, qsL, n4in);
    split_f32<<<n4in / 256, 256>>>(keys,    ksH, ksL, n4in);
    split_f32<<<n4in / 256, 256>>>(values,  vsH, vsL, n4in);
    const int n4w = DMOD * DMOD / 4;
    split_f32<<<n4w / 256, 256>>>(Wq, WqH, WqL, n4w);
    split_f32<<<n4w / 256, 256>>>(Wk, WkH, WkL, n4w);
    split_f32<<<n4w / 256, 256>>>(Wv, WvH, WvL, n4w);
    split_f32<<<n4w / 256, 256>>>(Wo, WoH, WoL, n4w);
    transpose_split<<<dim3(32, 32), dim3(32, 8)>>>(Wb, WbTH, WbTL);

    dim3 blk(256);
    dim3 gP(DMOD / 128, MR / 128, 1);   // 8 x 64

    bf_gemm<0><<<gP, blk, SM>>>(qsH, qsL, WqH, WqL, DMOD, 0, 0,
                                nullptr, nullptr, bq, nullptr, nullptr, QH, QL);
    bf_gemm<0><<<gP, blk, SM>>>(ksH, ksL, WkH, WkL, DMOD, 0, 0,
                                nullptr, nullptr, bk, nullptr, nullptr, KH, KL);
    bf_gemm<7><<<gP, blk, SM>>>(vsH, vsL, WvH, WvL, DMOD, 0, 0,
                                nullptr, nullptr, bv, nullptr, nullptr, VtH, VtL);
    bf_gemm<2><<<gP, blk, SM>>>(qsH, qsL, WbTH, WbTL, DMOD, 0, 0,
                                nullptr, nullptr, nullptr, nullptr, nullptr, XWH, XWL);
    bf_gemm<3><<<dim3(8, 8, Bb), blk, SM>>>(
        XWH, XWL, qsH, qsL, DMOD,
        (long long)NSEQ * DMOD, (long long)NSEQ * DMOD,
        Pout, gL, nullptr, bb, lam, nullptr, nullptr);
    bf_gemm<4><<<dim3(8, 8, Bb * Hh), blk, SM>>>(
        QH, QL, KH, KL, DHd,
        (long long)NSEQ * DHd, (long long)NSEQ * DHd,
        att, gL, nullptr, nullptr, nullptr, nullptr, nullptr);
    softmax_rows<<<(Bb * Hh * NSEQ) / 8, 256>>>(att);
    av_gemm<<<dim3(1, 8, Bb * Hh), blk, SM>>>(att, VtH, VtL, CATH, CATL);
    bf_gemm<6><<<gP, blk, SM>>>(CATH, CATL, WoH, WoL, DMOD, 0, 0,
                                out_main, nullptr, bo, nullptr, nullptr,
                                nullptr, nullptr);

    (void)in_sizes; (void)n_in; (void)out_size;
}

// round 7
// speedup vs baseline: 1.6918x; 1.0527x over previous
#include <cuda_runtime.h>
#include <cuda_bf16.h>
#include <stdint.h>
#include <math.h>

#define Bb    8
#define Hh    16
#define NSEQ  1024
#define DMOD  1024
#define DHd   64
#define MR    (Bb * NSEQ)
#define EPSF  1e-9f

typedef unsigned int u32;
typedef unsigned long long u64;
typedef __nv_bfloat16 bf16;

// ---------------- scratch (device globals; allocations forbidden) -----------
__device__ __align__(16) bf16 g_qsH[MR * DMOD], g_qsL[MR * DMOD];
__device__ __align__(16) bf16 g_ksH[MR * DMOD], g_ksL[MR * DMOD];
__device__ __align__(16) bf16 g_vsH[MR * DMOD], g_vsL[MR * DMOD];
__device__ __align__(16) bf16 g_WqH[DMOD * DMOD], g_WqL[DMOD * DMOD];
__device__ __align__(16) bf16 g_WkH[DMOD * DMOD], g_WkL[DMOD * DMOD];
__device__ __align__(16) bf16 g_WvH[DMOD * DMOD], g_WvL[DMOD * DMOD];
__device__ __align__(16) bf16 g_WoH[DMOD * DMOD], g_WoL[DMOD * DMOD];
__device__ __align__(16) bf16 g_WbTH[DMOD * DMOD], g_WbTL[DMOD * DMOD];
__device__ __align__(16) bf16 g_QH[MR * DMOD], g_QL[MR * DMOD];
__device__ __align__(16) bf16 g_KH[MR * DMOD], g_KL[MR * DMOD];
__device__ __align__(16) bf16 g_VtH[MR * DMOD], g_VtL[MR * DMOD];
__device__ __align__(16) bf16 g_XWH[MR * DMOD], g_XWL[MR * DMOD];
__device__ __align__(16) bf16 g_CATH[MR * DMOD], g_CATL[MR * DMOD];
__device__ float g_L[Bb * NSEQ * NSEQ];

// ---------------- helpers ----------------------------------------------------
__device__ __forceinline__ u32 smem_u32(const void* p) {
    u32 a;
    asm("{ .reg .u64 t; cvta.to.shared.u64 t, %1; cvt.u32.u64 %0, t; }"
        : "=r"(a) : "l"(p));
    return a;
}
__device__ __forceinline__ u32 pack2(bf16 a, bf16 b) {
    __nv_bfloat162 t; t.x = a; t.y = b;
    return *reinterpret_cast<u32*>(&t);
}
__device__ __forceinline__ void split1(float v, bf16& h, bf16& l) {
    h = __float2bfloat16(v);
    l = __float2bfloat16(v - __bfloat162float(h));
}
__device__ __forceinline__ void ldm4(u32 addr, u32& r0, u32& r1, u32& r2, u32& r3) {
    asm volatile("ldmatrix.sync.aligned.m8n8.x4.shared.b16 {%0,%1,%2,%3}, [%4];"
                 : "=r"(r0), "=r"(r1), "=r"(r2), "=r"(r3) : "r"(addr));
}
__device__ __forceinline__ void mma16816(float* c, const u32* a, u32 b0, u32 b1) {
    asm volatile(
        "mma.sync.aligned.m16n8k16.row.col.f32.bf16.bf16.f32 "
        "{%0,%1,%2,%3}, {%4,%5,%6,%7}, {%8,%9}, {%0,%1,%2,%3};"
        : "+f"(c[0]), "+f"(c[1]), "+f"(c[2]), "+f"(c[3])
        : "r"(a[0]), "r"(a[1]), "r"(a[2]), "r"(a[3]), "r"(b0), "r"(b1));
}
__device__ __forceinline__ void cpa16(u32 dst, const void* src) {
    asm volatile("cp.async.cg.shared.global [%0], [%1], 16;"
                 :: "r"(dst), "l"(src) : "memory");
}
__device__ __forceinline__ void cp_commit() {
    asm volatile("cp.async.commit_group;" ::: "memory");
}
__device__ __forceinline__ u32 swz64(u32 row, u32 ch) {
    return row * 64u + ((ch ^ ((row >> 1) & 3u)) << 4);
}
__device__ __forceinline__ u32 swz128(u32 row, u32 ch) {
    return row * 128u + ((ch ^ (row & 7u)) << 4);
}

// ---------------------------------------------------------------------------
__global__ void split_f32(const float* __restrict__ in, bf16* __restrict__ hi,
                          bf16* __restrict__ lo, int n4)
{
    int i = blockIdx.x * blockDim.x + threadIdx.x;
    if (i >= n4) return;
    float4 v = ((const float4*)in)[i];
    bf16 h0, h1, h2, h3, l0, l1, l2, l3;
    split1(v.x, h0, l0); split1(v.y, h1, l1);
    split1(v.z, h2, l2); split1(v.w, h3, l3);
    ((uint2*)hi)[i] = make_uint2(pack2(h0, h1), pack2(h2, h3));
    ((uint2*)lo)[i] = make_uint2(pack2(l0, l1), pack2(l2, l3));
}

__global__ void transpose_split(const float* __restrict__ in,
                                bf16* __restrict__ oh, bf16* __restrict__ ol)
{
    __shared__ float t[32][33];
    const int tx = threadIdx.x;
    const int x = blockIdx.x * 32 + tx;
    for (int i = threadIdx.y; i < 32; i += 8)
        t[i][tx] = in[(size_t)(blockIdx.y * 32 + i) * DMOD + x];
    __syncthreads();
    const int ox = blockIdx.y * 32 + tx;
    for (int i = threadIdx.y; i < 32; i += 8) {
        bf16 h, l;
        split1(t[tx][i], h, l);
        oh[(size_t)(blockIdx.x * 32 + i) * DMOD + ox] = h;
        ol[(size_t)(blockIdx.x * 32 + i) * DMOD + ox] = l;
    }
}

// ---------------------------------------------------------------------------
// Split-plane bf16 GEMM, K-chunk 32, 2-stage cp.async, 64KB smem, 2 CTAs/SM.
// ---------------------------------------------------------------------------
template<int EPI>
__global__ __launch_bounds__(256, 2)
void bf_gemm(const bf16* __restrict__ Ah, const bf16* __restrict__ Al,
             const bf16* __restrict__ Bh, const bf16* __restrict__ Bl,
             int K, long long sAz, long long sBz,
             float* __restrict__ out0, float* __restrict__ aux,
             const float* __restrict__ bias,
             const float* __restrict__ s0, const float* __restrict__ s1,
             bf16* __restrict__ oH, bf16* __restrict__ oL)
{
    constexpr int PA = 128 * 64;
    constexpr int AHI = 0, ALO = PA, BHI = 2 * PA, BLO = 3 * PA;
    constexpr int STAGE = 4 * PA;

    extern __shared__ char smem[];
    const u32 sb = smem_u32(smem);

    const int tid = threadIdx.x;
    const int wid = tid >> 5, lane = tid & 31;
    const int wM = wid & 1, wN = wid >> 1;
    const int z  = blockIdx.z;
    const int m0 = blockIdx.y * 128;
    const int n0 = blockIdx.x * 128;
    const int mat = lane >> 3, lir = lane & 7;
    const int rfr = (mat & 1) * 8 + lir;
    const int kcf = mat >> 1;

    const bf16* Abh = Ah + (size_t)z * sAz + (size_t)m0 * K;
    const bf16* Abl = Al + (size_t)z * sAz + (size_t)m0 * K;
    const bf16* Bbh = Bh + (size_t)z * sBz + (size_t)n0 * K;
    const bf16* Bbl = Bl + (size_t)z * sBz + (size_t)n0 * K;

    float acc[4][4][4];
#pragma unroll
    for (int i = 0; i < 4; i++)
#pragma unroll
        for (int j = 0; j < 4; j++)
#pragma unroll
            for (int e = 0; e < 4; e++) acc[i][j][e] = 0.0f;

    const int C = K >> 5;

    auto stage = [&](int c, int s) {
        const int k0 = c << 5;
        const u32 base = sb + (u32)s * STAGE;
#pragma unroll
        for (int u = tid; u < 512; u += 256) {
            const u32 row = (u32)(u >> 2), ch = (u32)(u & 3);
            const u32 off = swz64(row, ch);
            const size_t so = (size_t)row * K + k0 + ch * 8;
            cpa16(base + AHI + off, Abh + so);
            cpa16(base + ALO + off, Abl + so);
            cpa16(base + BHI + off, Bbh + so);
            cpa16(base + BLO + off, Bbl + so);
        }
        cp_commit();
    };

    stage(0, 0);
    for (int c = 0; c < C; c++) {
        if (c + 1 < C) {
            stage(c + 1, (c + 1) & 1);
            asm volatile("cp.async.wait_group 1;" ::: "memory");
        } else {
            asm volatile("cp.async.wait_group 0;" ::: "memory");
        }
        __syncthreads();
        const u32 bbase = sb + (u32)(c & 1) * STAGE;

#pragma unroll
        for (int ks = 0; ks < 2; ks++) {
            const u32 kch = (u32)(ks * 2 + kcf);
            u32 ah[4][4], al[4][4], bx[2][4];
#pragma unroll
            for (int mi = 0; mi < 4; mi++) {
                const u32 row = (u32)(wM * 64 + mi * 16 + rfr);
                ldm4(bbase + AHI + swz64(row, kch),
                     ah[mi][0], ah[mi][1], ah[mi][2], ah[mi][3]);
            }
#pragma unroll
            for (int j = 0; j < 2; j++) {
                const u32 row = (u32)(wN * 32 + j * 16 + rfr);
                ldm4(bbase + BHI + swz64(row, kch),
                     bx[j][0], bx[j][1], bx[j][2], bx[j][3]);
            }
#pragma unroll
            for (int mi = 0; mi < 4; mi++)
#pragma unroll
                for (int ni = 0; ni < 4; ni++)
                    mma16816(acc[mi][ni], ah[mi],
                             bx[ni >> 1][ni & 1], bx[ni >> 1][(ni & 1) + 2]);
#pragma unroll
            for (int mi = 0; mi < 4; mi++) {
                const u32 row = (u32)(wM * 64 + mi * 16 + rfr);
                ldm4(bbase + ALO + swz64(row, kch),
                     al[mi][0], al[mi][1], al[mi][2], al[mi][3]);
            }
#pragma unroll
            for (int mi = 0; mi < 4; mi++)
#pragma unroll
                for (int ni = 0; ni < 4; ni++)
                    mma16816(acc[mi][ni], al[mi],
                             bx[ni >> 1][ni & 1], bx[ni >> 1][(ni & 1) + 2]);
#pragma unroll
            for (int j = 0; j < 2; j++) {
                const u32 row = (u32)(wN * 32 + j * 16 + rfr);
                ldm4(bbase + BLO + swz64(row, kch),
                     bx[j][0], bx[j][1], bx[j][2], bx[j][3]);
            }
#pragma unroll
            for (int mi = 0; mi < 4; mi++)
#pragma unroll
                for (int ni = 0; ni < 4; ni++)
                    mma16816(acc[mi][ni], ah[mi],
                             bx[ni >> 1][ni & 1], bx[ni >> 1][(ni & 1) + 2]);
        }
        __syncthreads();
    }

    const int gid = lane >> 2, t4 = lane & 3;
#pragma unroll
    for (int mi = 0; mi < 4; mi++) {
#pragma unroll
        for (int h = 0; h < 2; h++) {
            const int m = m0 + wM * 64 + mi * 16 + gid + h * 8;
#pragma unroll
            for (int ni = 0; ni < 4; ni++) {
                const int n = n0 + wN * 32 + ni * 8 + t4 * 2;
                float v0 = acc[mi][ni][h * 2 + 0];
                float v1 = acc[mi][ni][h * 2 + 1];

                if (EPI == 0) {
                    const int b = m >> 10, tok = m & 1023;
                    const int hd = n >> 6, d = n & 63;
                    bf16 h0, l0, h1, l1;
                    split1(v0 + bias[n], h0, l0);
                    split1(v1 + bias[n + 1], h1, l1);
                    const size_t ix = (((size_t)(b * Hh + hd) * NSEQ) + tok) * DHd + d;
                    *(u32*)(oH + ix) = pack2(h0, h1);
                    *(u32*)(oL + ix) = pack2(l0, l1);
                } else if (EPI == 7) {
                    const int b = m >> 10, tok = m & 1023;
                    const int hd = n >> 6, d = n & 63;
                    bf16 h0, l0, h1, l1;
                    split1(v0 + bias[n], h0, l0);
                    split1(v1 + bias[n + 1], h1, l1);
                    const size_t zz = (size_t)(b * Hh + hd);
                    oH[(zz * DHd + d) * NSEQ + tok]     = h0;
                    oH[(zz * DHd + d + 1) * NSEQ + tok] = h1;
                    oL[(zz * DHd + d) * NSEQ + tok]     = l0;
                    oL[(zz * DHd + d + 1) * NSEQ + tok] = l1;
                } else if (EPI == 2) {
                    bf16 h0, l0, h1, l1;
                    split1(v0, h0, l0); split1(v1, h1, l1);
                    const size_t ix = (size_t)m * DMOD + n;
                    *(u32*)(oH + ix) = pack2(h0, h1);
                    *(u32*)(oL + ix) = pack2(l0, l1);
                } else if (EPI == 3) {
                    const float bb0 = s0[0], lam = s1[0];
                    float p0 = 1.0f / (1.0f + __expf(-(v0 + bb0)));
                    float p1 = 1.0f / (1.0f + __expf(-(v1 + bb0)));
                    const size_t idx = ((size_t)z * NSEQ + m) * NSEQ + n;
                    *(float2*)(out0 + idx) = make_float2(p0, p1);
                    *(float2*)(aux + idx) =
                        make_float2(lam * __logf(p0 + EPSF), lam * __logf(p1 + EPSF));
                } else if (EPI == 6) {
                    *(float2*)(out0 + (size_t)m * DMOD + n) =
                        make_float2(v0 + bias[n], v1 + bias[n + 1]);
                }
            }
        }
    }
}

// ---------------------------------------------------------------------------
// Fused logits + softmax. CTA = 16 q-rows x full 1024 keys for one z.
// acc[8 chunks][2 nf][4] = 64 fp32/thread. Writes normalized att directly.
// smem: A planes 4KB | K chunks double-buffered 64KB | reductions 1KB
// ---------------------------------------------------------------------------
__global__ __launch_bounds__(256, 2)
void logits_softmax(const bf16* __restrict__ Qh, const bf16* __restrict__ Ql,
                    const bf16* __restrict__ Kh, const bf16* __restrict__ Kl,
                    const float* __restrict__ Lbuf, float* __restrict__ att)
{
    constexpr int S_AH = 0, S_AL = 2048, S_B = 4096;
    constexpr int BSTG = 32768;                 // per stage (hi 16KB + lo 16KB)
    constexpr int S_WMAX = S_B + 2 * BSTG;      // 69632: [16][8] fp32
    constexpr int S_WSUM = S_WMAX + 512;        // [16][8] fp32

    extern __shared__ char smem[];
    const u32 sb = smem_u32(smem);

    const int tid = threadIdx.x;
    const int wid = tid >> 5, lane = tid & 31;
    const int z = blockIdx.y, bz = z >> 4;
    const int m0 = blockIdx.x * 16;
    const int mat = lane >> 3, lir = lane & 7;
    const int rfr = (mat & 1) * 8 + lir;
    const int kcf = mat >> 1;

    const bf16* Abh = Qh + (size_t)z * NSEQ * DHd + (size_t)m0 * DHd;
    const bf16* Abl = Ql + (size_t)z * NSEQ * DHd + (size_t)m0 * DHd;
    const bf16* Kbh = Kh + (size_t)z * NSEQ * DHd;
    const bf16* Kbl = Kl + (size_t)z * NSEQ * DHd;

    // load A (Q tile, 16 rows x 64 d, both planes)
    if (tid < 128) {
        const u32 row = (u32)(tid >> 3), ch = (u32)(tid & 7);
        const u32 off = swz128(row, ch);
        cpa16(sb + S_AH + off, Abh + (size_t)row * DHd + ch * 8);
        cpa16(sb + S_AL + off, Abl + (size_t)row * DHd + ch * 8);
    }

    auto stageK = [&](int j, int s) {
        const u32 base = sb + S_B + (u32)s * BSTG;
#pragma unroll
        for (int u = tid; u < 1024; u += 256) {
            const u32 row = (u32)(u >> 3), ch = (u32)(u & 7);
            const u32 off = swz128(row, ch);
            const size_t so = (size_t)(j * 128 + row) * DHd + ch * 8;
            cpa16(base + off, Kbh + so);
            cpa16(base + 16384 + off, Kbl + so);
        }
        cp_commit();
    };

    float acc[8][2][4];
#pragma unroll
    for (int j = 0; j < 8; j++)
#pragma unroll
        for (int n = 0; n < 2; n++)
#pragma unroll
            for (int e = 0; e < 4; e++) acc[j][n][e] = 0.0f;

    stageK(0, 0);
#pragma unroll
    for (int j = 0; j < 8; j++) {
        if (j < 7) {
            stageK(j + 1, (j + 1) & 1);
            asm volatile("cp.async.wait_group 1;" ::: "memory");
        } else {
            asm volatile("cp.async.wait_group 0;" ::: "memory");
        }
        __syncthreads();
        const u32 bbase = sb + S_B + (u32)(j & 1) * BSTG;

#pragma unroll
        for (int ks = 0; ks < 4; ks++) {
            const u32 kch = (u32)(ks * 2 + kcf);
            u32 a_h[4], a_l[4], b_h[4], b_l[4];
            ldm4(sb + S_AH + swz128((u32)rfr, kch), a_h[0], a_h[1], a_h[2], a_h[3]);
            const u32 brow = (u32)(wid * 16 + rfr);
            ldm4(bbase + swz128(brow, kch), b_h[0], b_h[1], b_h[2], b_h[3]);
            ldm4(sb + S_AL + swz128((u32)rfr, kch), a_l[0], a_l[1], a_l[2], a_l[3]);
            ldm4(bbase + 16384 + swz128(brow, kch), b_l[0], b_l[1], b_l[2], b_l[3]);
#pragma unroll
            for (int ni = 0; ni < 2; ni++) {
                mma16816(acc[j][ni], a_h, b_h[ni], b_h[ni + 2]);
                mma16816(acc[j][ni], a_l, b_h[ni], b_h[ni + 2]);
                mma16816(acc[j][ni], a_h, b_l[ni], b_l[ni + 2]);
            }
        }
        __syncthreads();
    }

    // ---- add L, softmax, write ----
    const int gid = lane >> 2, t4 = lane & 3;
    float* wmax = (float*)(smem + (S_WMAX - 0));
    float* wsum = (float*)(smem + (S_WSUM - 0));

    float mx[2] = {-3.4e38f, -3.4e38f};
#pragma unroll
    for (int j = 0; j < 8; j++)
#pragma unroll
        for (int ni = 0; ni < 2; ni++) {
            const int col = j * 128 + wid * 16 + ni * 8 + t4 * 2;
#pragma unroll
            for (int h = 0; h < 2; h++) {
                const int row = m0 + gid + h * 8;
                float2 Lv = *(const float2*)(Lbuf + ((size_t)bz * NSEQ + row) * NSEQ + col);
                float s0 = acc[j][ni][h * 2 + 0] * 0.125f + Lv.x;
                float s1 = acc[j][ni][h * 2 + 1] * 0.125f + Lv.y;
                acc[j][ni][h * 2 + 0] = s0;
                acc[j][ni][h * 2 + 1] = s1;
                mx[h] = fmaxf(mx[h], fmaxf(s0, s1));
            }
        }
#pragma unroll
    for (int h = 0; h < 2; h++) {
        mx[h] = fmaxf(mx[h], __shfl_xor_sync(0xffffffffu, mx[h], 1));
        mx[h] = fmaxf(mx[h], __shfl_xor_sync(0xffffffffu, mx[h], 2));
        if (t4 == 0) wmax[(gid + h * 8) * 8 + wid] = mx[h];
    }
    __syncthreads();
    float rmax[2];
#pragma unroll
    for (int h = 0; h < 2; h++) {
        float m = wmax[(gid + h * 8) * 8 + 0];
#pragma unroll
        for (int w = 1; w < 8; w++) m = fmaxf(m, wmax[(gid + h * 8) * 8 + w]);
        rmax[h] = m;
    }
    float sm[2] = {0.0f, 0.0f};
#pragma unroll
    for (int j = 0; j < 8; j++)
#pragma unroll
        for (int ni = 0; ni < 2; ni++)
#pragma unroll
            for (int h = 0; h < 2; h++) {
                float e0 = __expf(acc[j][ni][h * 2 + 0] - rmax[h]);
                float e1 = __expf(acc[j][ni][h * 2 + 1] - rmax[h]);
                acc[j][ni][h * 2 + 0] = e0;
                acc[j][ni][h * 2 + 1] = e1;
                sm[h] += e0 + e1;
            }
#pragma unroll
    for (int h = 0; h < 2; h++) {
        sm[h] += __shfl_xor_sync(0xffffffffu, sm[h], 1);
        sm[h] += __shfl_xor_sync(0xffffffffu, sm[h], 2);
        if (t4 == 0) wsum[(gid + h * 8) * 8 + wid] = sm[h];
    }
    __syncthreads();
    float rinv[2];
#pragma unroll
    for (int h = 0; h < 2; h++) {
        float s = 0.0f;
#pragma unroll
        for (int w = 0; w < 8; w++) s += wsum[(gid + h * 8) * 8 + w];
        rinv[h] = 1.0f / s;
    }
#pragma unroll
    for (int j = 0; j < 8; j++)
#pragma unroll
        for (int ni = 0; ni < 2; ni++) {
            const int col = j * 128 + wid * 16 + ni * 8 + t4 * 2;
#pragma unroll
            for (int h = 0; h < 2; h++) {
                const int row = m0 + gid + h * 8;
                *(float2*)(att + ((size_t)z * NSEQ + row) * NSEQ + col) =
                    make_float2(acc[j][ni][h * 2 + 0] * rinv[h],
                                acc[j][ni][h * 2 + 1] * rinv[h]);
            }
        }
}

// ---------------------------------------------------------------------------
// AV GEMM (unchanged from R6)
// ---------------------------------------------------------------------------
__global__ __launch_bounds__(256, 2)
void av_gemm(const float* __restrict__ att,
             const bf16* __restrict__ Vth, const bf16* __restrict__ Vtl,
             bf16* __restrict__ oH, bf16* __restrict__ oL)
{
    constexpr int S_B = 32768, S_CH = 49152, S_CL = 57344;
    extern __shared__ char smem[];
    const u32 sb = smem_u32(smem);

    const int tid = threadIdx.x;
    const int wid = tid >> 5, lane = tid & 31;
    const int wM = wid & 3, wN = wid >> 2;
    const int z = blockIdx.z, m0 = blockIdx.y * 128;
    const int bz = z >> 4, hz = z & 15;
    const int mat = lane >> 3, lir = lane & 7;
    const int rfr = (mat & 1) * 8 + lir, kcf = mat >> 1;

    const float* Ab = att + (size_t)z * NSEQ * NSEQ + (size_t)m0 * NSEQ;
    const bf16* Bh = Vth + (size_t)z * DHd * NSEQ;
    const bf16* Bl = Vtl + (size_t)z * DHd * NSEQ;

    float acc[2][4][4];
#pragma unroll
    for (int i = 0; i < 2; i++)
#pragma unroll
        for (int j = 0; j < 4; j++)
#pragma unroll
            for (int e = 0; e < 4; e++) acc[i][j][e] = 0.0f;

    auto stage = [&](int c, int s) {
        const int k0 = c << 5;
        const u32 araw = sb + (u32)s * 16384;
#pragma unroll
        for (int u = tid; u < 1024; u += 256) {
            const u32 row = (u32)(u >> 3), ch = (u32)(u & 7);
            cpa16(araw + row * 128 + ch * 16, Ab + (size_t)row * NSEQ + k0 + ch * 4);
        }
        const u32 bbs = sb + S_B + (u32)s * 8192;
#pragma unroll
        for (int u = tid; u < 256; u += 256) {
            const u32 row = (u32)(u >> 2), ch = (u32)(u & 3);
            const u32 off = swz64(row, ch);
            const size_t so = (size_t)row * NSEQ + k0 + ch * 8;
            cpa16(bbs + off, Bh + so);
            cpa16(bbs + 4096 + off, Bl + so);
        }
        cp_commit();
    };

    stage(0, 0);
    for (int c = 0; c < 32; c++) {
        if (c < 31) {
            stage(c + 1, (c + 1) & 1);
            asm volatile("cp.async.wait_group 1;" ::: "memory");
        } else {
            asm volatile("cp.async.wait_group 0;" ::: "memory");
        }
        __syncthreads();
        const char* araw = smem + (c & 1) * 16384;
#pragma unroll
        for (int u = tid; u < 1024; u += 256) {
            const u32 row = (u32)(u >> 3), q = (u32)(u & 7);
            float4 v = *(const float4*)(araw + row * 128 + q * 16);
            bf16 h0, h1, h2, h3, l0, l1, l2, l3;
            split1(v.x, h0, l0); split1(v.y, h1, l1);
            split1(v.z, h2, l2); split1(v.w, h3, l3);
            const u32 off = swz64(row, q >> 1) + (q & 1) * 8;
            *(uint2*)(smem + S_CH + off) = make_uint2(pack2(h0, h1), pack2(h2, h3));
            *(uint2*)(smem + S_CL + off) = make_uint2(pack2(l0, l1), pack2(l2, l3));
        }
        __syncthreads();

        const u32 bbs = sb + S_B + (u32)(c & 1) * 8192;
#pragma unroll
        for (int ks = 0; ks < 2; ks++) {
            const u32 kch = (u32)(ks * 2 + kcf);
            u32 ah[2][4], al[2][4], bx[2][4];
#pragma unroll
            for (int mi = 0; mi < 2; mi++) {
                const u32 row = (u32)(wM * 32 + mi * 16 + rfr);
                ldm4(sb + S_CH + swz64(row, kch),
                     ah[mi][0], ah[mi][1], ah[mi][2], ah[mi][3]);
            }
#pragma unroll
            for (int j = 0; j < 2; j++) {
                const u32 row = (u32)(wN * 32 + j * 16 + rfr);
                ldm4(bbs + swz64(row, kch), bx[j][0], bx[j][1], bx[j][2], bx[j][3]);
            }
#pragma unroll
            for (int mi = 0; mi < 2; mi++)
#pragma unroll
                for (int ni = 0; ni < 4; ni++)
                    mma16816(acc[mi][ni], ah[mi],
                             bx[ni >> 1][ni & 1], bx[ni >> 1][(ni & 1) + 2]);
#pragma unroll
            for (int mi = 0; mi < 2; mi++) {
                const u32 row = (u32)(wM * 32 + mi * 16 + rfr);
                ldm4(sb + S_CL + swz64(row, kch),
                     al[mi][0], al[mi][1], al[mi][2], al[mi][3]);
            }
#pragma unroll
            for (int mi = 0; mi < 2; mi++)
#pragma unroll
                for (int ni = 0; ni < 4; ni++)
                    mma16816(acc[mi][ni], al[mi],
                             bx[ni >> 1][ni & 1], bx[ni >> 1][(ni & 1) + 2]);
#pragma unroll
            for (int j = 0; j < 2; j++) {
                const u32 row = (u32)(wN * 32 + j * 16 + rfr);
                ldm4(bbs + 4096 + swz64(row, kch),
                     bx[j][0], bx[j][1], bx[j][2], bx[j][3]);
            }
#pragma unroll
            for (int mi = 0; mi < 2; mi++)
#pragma unroll
                for (int ni = 0; ni < 4; ni++)
                    mma16816(acc[mi][ni], ah[mi],
                             bx[ni >> 1][ni & 1], bx[ni >> 1][(ni & 1) + 2]);
        }
        __syncthreads();
    }

    const int gid = lane >> 2, t4 = lane & 3;
#pragma unroll
    for (int mi = 0; mi < 2; mi++) {
#pragma unroll
        for (int h = 0; h < 2; h++) {
            const int m = m0 + wM * 32 + mi * 16 + gid + h * 8;
#pragma unroll
            for (int ni = 0; ni < 4; ni++) {
                const int n = wN * 32 + ni * 8 + t4 * 2;
                bf16 h0, l0, h1, l1;
                split1(acc[mi][ni][h * 2 + 0], h0, l0);
                split1(acc[mi][ni][h * 2 + 1], h1, l1);
                const size_t ix = ((size_t)bz * NSEQ + m) * DMOD + hz * DHd + n;
                *(u32*)(oH + ix) = pack2(h0, h1);
                *(u32*)(oL + ix) = pack2(l0, l1);
            }
        }
    }
}

// ---------------------------------------------------------------------------
extern "C" void kernel_launch(void* const* d_in, const int* in_sizes, int n_in,
                              void* d_out, int out_size)
{
    const float* queries = (const float*)d_in[0];
    const float* keys    = (const float*)d_in[1];
    const float* values  = (const float*)d_in[2];
    const float* Wq = (const float*)d_in[3];  const float* bq = (const float*)d_in[4];
    const float* Wk = (const float*)d_in[5];  const float* bk = (const float*)d_in[6];
    const float* Wv = (const float*)d_in[7];  const float* bv = (const float*)d_in[8];
    const float* Wo = (const float*)d_in[9];  const float* bo = (const float*)d_in[10];
    const float* Wb = (const float*)d_in[11]; const float* bb = (const float*)d_in[12];
    const float* lam = (const float*)d_in[13];

    float* out_main = (float*)d_out;
    float* att      = out_main + (size_t)Bb * NSEQ * DMOD;
    float* Pout     = att + (size_t)Bb * Hh * NSEQ * NSEQ;

#define GA(sym, var) bf16* var; cudaGetSymbolAddress((void**)&var, sym)
    GA(g_qsH, qsH); GA(g_qsL, qsL); GA(g_ksH, ksH); GA(g_ksL, ksL);
    GA(g_vsH, vsH); GA(g_vsL, vsL);
    GA(g_WqH, WqH); GA(g_WqL, WqL); GA(g_WkH, WkH); GA(g_WkL, WkL);
    GA(g_WvH, WvH); GA(g_WvL, WvL); GA(g_WoH, WoH); GA(g_WoL, WoL);
    GA(g_WbTH, WbTH); GA(g_WbTL, WbTL);
    GA(g_QH, QH); GA(g_QL, QL); GA(g_KH, KH); GA(g_KL, KL);
    GA(g_VtH, VtH); GA(g_VtL, VtL);
    GA(g_XWH, XWH); GA(g_XWL, XWL);
    GA(g_CATH, CATH); GA(g_CATL, CATL);
#undef GA
    float* gL; cudaGetSymbolAddress((void**)&gL, g_L);

    const int SM = 65536;
    const int SM_LS = 70656;
    cudaFuncSetAttribute(bf_gemm<0>, cudaFuncAttributeMaxDynamicSharedMemorySize, SM);
    cudaFuncSetAttribute(bf_gemm<2>, cudaFuncAttributeMaxDynamicSharedMemorySize, SM);
    cudaFuncSetAttribute(bf_gemm<3>, cudaFuncAttributeMaxDynamicSharedMemorySize, SM);
    cudaFuncSetAttribute(bf_gemm<6>, cudaFuncAttributeMaxDynamicSharedMemorySize, SM);
    cudaFuncSetAttribute(bf_gemm<7>, cudaFuncAttributeMaxDynamicSharedMemorySize, SM);
    cudaFuncSetAttribute(av_gemm,    cudaFuncAttributeMaxDynamicSharedMemorySize, SM);
    cudaFuncSetAttribute(logits_softmax, cudaFuncAttributeMaxDynamicSharedMemorySize, SM_LS);

    dim3 blk(256);
    dim3 gP(DMOD / 128, MR / 128, 1);
    const int n4in = MR * DMOD / 4;
    const int n4w = DMOD * DMOD / 4;

    // Ordered so ncu (-s 5 -c 1) captures launch #6 = GEMM-K (projection GEMM)
    split_f32<<<n4in / 256, 256>>>(queries, qsH, qsL, n4in);         // 1
    split_f32<<<n4w / 256, 256>>>(Wq, WqH, WqL, n4w);                // 2
    bf_gemm<0><<<gP, blk, SM>>>(qsH, qsL, WqH, WqL, DMOD, 0, 0,      // 3
                                nullptr, nullptr, bq, nullptr, nullptr, QH, QL);
    split_f32<<<n4in / 256, 256>>>(keys, ksH, ksL, n4in);            // 4
    split_f32<<<n4w / 256, 256>>>(Wk, WkH, WkL, n4w);                // 5
    bf_gemm<0><<<gP, blk, SM>>>(ksH, ksL, WkH, WkL, DMOD, 0, 0,      // 6  <- ncu
                                nullptr, nullptr, bk, nullptr, nullptr, KH, KL);
    split_f32<<<n4in / 256, 256>>>(values, vsH, vsL, n4in);          // 7
    split_f32<<<n4w / 256, 256>>>(Wv, WvH, WvL, n4w);                // 8
    bf_gemm<7><<<gP, blk, SM>>>(vsH, vsL, WvH, WvL, DMOD, 0, 0,      // 9
                                nullptr, nullptr, bv, nullptr, nullptr, VtH, VtL);
    split_f32<<<n4w / 256, 256>>>(Wo, WoH, WoL, n4w);                // 10
    transpose_split<<<dim3(32, 32), dim3(32, 8)>>>(Wb, WbTH, WbTL);  // 11
    bf_gemm<2><<<gP, blk, SM>>>(qsH, qsL, WbTH, WbTL, DMOD, 0, 0,    // 12
                                nullptr, nullptr, nullptr, nullptr, nullptr, XWH, XWL);
    bf_gemm<3><<<dim3(8, 8, Bb), blk, SM>>>(                         // 13
        XWH, XWL, qsH, qsL, DMOD,
        (long long)NSEQ * DMOD, (long long)NSEQ * DMOD,
        Pout, gL, nullptr, bb, lam, nullptr, nullptr);
    logits_softmax<<<dim3(64, 128), blk, SM_LS>>>(QH, QL, KH, KL, gL, att);  // 14
    av_gemm<<<dim3(1, 8, Bb * Hh), blk, SM>>>(att, VtH, VtL, CATH, CATL);    // 15
    bf_gemm<6><<<gP, blk, SM>>>(CATH, CATL, WoH, WoL, DMOD, 0, 0,            // 16
                                out_main, nullptr, bo, nullptr, nullptr,
                                nullptr, nullptr);

    (void)in_sizes; (void)n_in; (void)out_size;
}